// round 1
// baseline (speedup 1.0000x reference)
#include <cuda_runtime.h>
#include <math.h>

#define L 512
#define DO 64      // D_ORIG
#define NH 8
#define DH 32
#define DE 256
#define SCALE 0.17677669529663687f  // 1/sqrt(32)

// Scratch (device globals — no allocations allowed)
__device__ float g_q[L*DE];
__device__ float g_k[L*DE];
__device__ float g_v[L*DE];
__device__ float g_p[L*512];          // [i][n*64+c]
__device__ float g_sc[(size_t)NH*L*L]; // [n][i][j] : qk base, then full scores
__device__ float g_m[L*NH];
__device__ float g_s[L*NH];
__device__ float g_w[L*512];          // [i][n*64+c], unnormalized
__device__ float g_att[L*DE];         // unnormalized attn@v

// ---------------------------------------------------------------------------
// Kernel 1: projections q,k,v = x@W and p[i][n][c] = scale * sum_d We[c][n*32+d]*q[i][n*32+d]
// ---------------------------------------------------------------------------
__global__ void proj_kernel(const float* __restrict__ x, const float* __restrict__ Wq,
                            const float* __restrict__ Wk, const float* __restrict__ Wv,
                            const float* __restrict__ We) {
    int i = blockIdx.x, t = threadIdx.x;
    __shared__ float xs[DO];
    __shared__ float qs[DE];
    if (t < DO) xs[t] = x[i*DO + t];
    __syncthreads();
    float aq = 0.f, ak = 0.f, av = 0.f;
    #pragma unroll
    for (int d = 0; d < DO; d++) {
        float xv = xs[d];
        aq = fmaf(xv, Wq[d*DE + t], aq);
        ak = fmaf(xv, Wk[d*DE + t], ak);
        av = fmaf(xv, Wv[d*DE + t], av);
    }
    g_q[i*DE + t] = aq; g_k[i*DE + t] = ak; g_v[i*DE + t] = av;
    qs[t] = aq;
    __syncthreads();
    #pragma unroll
    for (int r = t; r < 512; r += 256) {
        int n = r >> 6, c = r & 63;
        float acc = 0.f;
        const float* wrow = &We[c*DE + n*DH];
        const float* qh   = &qs[n*DH];
        #pragma unroll
        for (int d = 0; d < DH; d++) acc = fmaf(wrow[d], qh[d], acc);
        g_p[i*512 + r] = acc * SCALE;
    }
}

// ---------------------------------------------------------------------------
// Kernel 2: base[n][i][j] = scale * q[i,nslice] . k[j,nslice]
// ---------------------------------------------------------------------------
__global__ void qk_kernel() {
    int n = blockIdx.z, i0 = blockIdx.y * 32, j0 = blockIdx.x * 32;
    int t = threadIdx.x;
    __shared__ float Qs[32][33], Ks[32][33];
    for (int l = t; l < 1024; l += 256) {
        int r = l >> 5, d = l & 31;
        Qs[r][d] = g_q[(i0 + r)*DE + n*DH + d];
        Ks[r][d] = g_k[(j0 + r)*DE + n*DH + d];
    }
    __syncthreads();
    int tx = t & 31, ty = t >> 5;  // ty 0..7
    float acc[4] = {0.f, 0.f, 0.f, 0.f};
    #pragma unroll
    for (int d = 0; d < 32; d++) {
        float kv = Ks[tx][d];
        #pragma unroll
        for (int m = 0; m < 4; m++) acc[m] = fmaf(Qs[ty*4 + m][d], kv, acc[m]);
    }
    #pragma unroll
    for (int m = 0; m < 4; m++)
        g_sc[((size_t)n*L + (i0 + ty*4 + m))*L + j0 + tx] = acc[m] * SCALE;
}

// ---------------------------------------------------------------------------
// Kernel 3 (hot): per-query fused edge logits + online softmax + w accumulation.
// 1 CTA per i. 8 warps, warp w owns head n=w. e[i,:,:] streamed ONCE.
// ---------------------------------------------------------------------------
__global__ void attn_edge_kernel(const float* __restrict__ e) {
    int i = blockIdx.x, t = threadIdx.x;
    int w = t >> 5, lane = t & 31;
    __shared__ float ps[512];
    __shared__ float es[64][65];     // padded: conflict-free for both access patterns
    __shared__ float pes[8][64];
    ps[t] = g_p[i*512 + t];
    ps[t + 256] = g_p[i*512 + t + 256];
    float m = -1e30f, s = 0.f, wlo = 0.f, whi = 0.f;
    const float* pn = &ps[w*64];

    for (int j0 = 0; j0 < L; j0 += 64) {
        __syncthreads();
        // load e[i][j0:j0+64][0:64] (16 KB) cooperatively, float4 from gmem
        const float4* esrc = (const float4*)&e[((size_t)i*L + j0)*DO];
        for (int l = t; l < 1024; l += 256) {
            int jj = l >> 4, c4 = l & 15;
            float4 v4 = esrc[jj*16 + c4];
            es[jj][c4*4 + 0] = v4.x; es[jj][c4*4 + 1] = v4.y;
            es[jj][c4*4 + 2] = v4.z; es[jj][c4*4 + 3] = v4.w;
        }
        __syncthreads();

        // scores: head w, j = j0+lane and j0+lane+32
        size_t base = ((size_t)w*L + i)*L + j0;
        float sc0 = g_sc[base + lane];
        float sc1 = g_sc[base + lane + 32];
        #pragma unroll
        for (int c = 0; c < 64; c++) {
            float pv = pn[c];
            sc0 = fmaf(es[lane][c],      pv, sc0);
            sc1 = fmaf(es[lane + 32][c], pv, sc1);
        }
        g_sc[base + lane]      = sc0;
        g_sc[base + lane + 32] = sc1;

        // online softmax (per warp)
        float bm = fmaxf(sc0, sc1);
        #pragma unroll
        for (int off = 16; off; off >>= 1) bm = fmaxf(bm, __shfl_xor_sync(0xffffffffu, bm, off));
        float newm = fmaxf(m, bm);
        float alpha = __expf(m - newm);
        s *= alpha; wlo *= alpha; whi *= alpha;
        float pe0 = __expf(sc0 - newm), pe1 = __expf(sc1 - newm);
        pes[w][lane] = pe0; pes[w][lane + 32] = pe1;
        float bs = pe0 + pe1;
        #pragma unroll
        for (int off = 16; off; off >>= 1) bs += __shfl_xor_sync(0xffffffffu, bs, off);
        s += bs;
        m = newm;
        __syncwarp();

        // w += sum_j pe[j] * e[j][:]
        #pragma unroll
        for (int jj = 0; jj < 64; jj++) {
            float pv = pes[w][jj];
            wlo = fmaf(pv, es[jj][lane],      wlo);
            whi = fmaf(pv, es[jj][lane + 32], whi);
        }
    }
    g_w[i*512 + w*64 + lane]      = wlo;
    g_w[i*512 + w*64 + lane + 32] = whi;
    if (lane == 0) { g_m[i*NH + w] = m; g_s[i*NH + w] = s; }
}

// ---------------------------------------------------------------------------
// Kernel 4: out_unnorm[i][n*32+d] = sum_j exp(sc[n][i][j] - m[i][n]) * v[j][n*32+d]
// ---------------------------------------------------------------------------
__global__ void av_kernel() {
    int n = blockIdx.y, i0 = blockIdx.x * 32;
    int t = threadIdx.x, tx = t & 31, ty = t >> 5;
    __shared__ float Ps[32][65];
    __shared__ float Vs[64][33];
    __shared__ float ms[32];
    if (t < 32) ms[t] = g_m[(i0 + t)*NH + n];
    float acc[4] = {0.f, 0.f, 0.f, 0.f};
    for (int j0 = 0; j0 < L; j0 += 64) {
        __syncthreads();
        for (int l = t; l < 2048; l += 256) {
            int r = l >> 6, jj = l & 63;
            float sc = g_sc[((size_t)n*L + i0 + r)*L + j0 + jj];
            Ps[r][jj] = __expf(sc - ms[r]);
        }
        for (int l = t; l < 2048; l += 256) {
            int jj = l >> 5, d = l & 31;
            Vs[jj][d] = g_v[(j0 + jj)*DE + n*DH + d];
        }
        __syncthreads();
        #pragma unroll
        for (int jj = 0; jj < 64; jj++) {
            float vv = Vs[jj][tx];
            #pragma unroll
            for (int mm = 0; mm < 4; mm++) acc[mm] = fmaf(Ps[ty*4 + mm][jj], vv, acc[mm]);
        }
    }
    #pragma unroll
    for (int mm = 0; mm < 4; mm++)
        g_att[(i0 + ty*4 + mm)*DE + n*DH + tx] = acc[mm];
}

// ---------------------------------------------------------------------------
// Kernel 5: att = (attv + w@We_slice)/s ; out = att@Wo + bo
// ---------------------------------------------------------------------------
__global__ void out_kernel(const float* __restrict__ We, const float* __restrict__ Wo,
                           const float* __restrict__ bo, float* __restrict__ out) {
    int i = blockIdx.x, t = threadIdx.x;
    int n = t >> 5;  // head of embedding column t (32 dims per head)
    __shared__ float att[DE];
    __shared__ float ws[512];
    ws[t] = g_w[i*512 + t];
    ws[t + 256] = g_w[i*512 + t + 256];
    __syncthreads();
    float edge = 0.f;
    const float* wn = &ws[n*64];
    #pragma unroll
    for (int c = 0; c < 64; c++) edge = fmaf(wn[c], We[c*DE + t], edge);
    float sv = g_s[i*NH + n];
    att[t] = (g_att[i*DE + t] + edge) / sv;
    __syncthreads();
    if (t < DO) {
        float o = bo[t];
        #pragma unroll 8
        for (int k = 0; k < DE; k++) o = fmaf(att[k], Wo[k*DO + t], o);
        out[i*DO + t] = o;
    }
}

// ---------------------------------------------------------------------------
extern "C" void kernel_launch(void* const* d_in, const int* in_sizes, int n_in,
                              void* d_out, int out_size) {
    const float* x  = (const float*)d_in[0];
    const float* e  = (const float*)d_in[1];
    const float* Wq = (const float*)d_in[2];
    const float* Wk = (const float*)d_in[3];
    const float* Wv = (const float*)d_in[4];
    const float* We = (const float*)d_in[5];
    const float* Wo = (const float*)d_in[6];
    const float* bo = (const float*)d_in[7];
    float* out = (float*)d_out;

    proj_kernel<<<512, 256>>>(x, Wq, Wk, Wv, We);
    qk_kernel<<<dim3(16, 16, 8), 256>>>();
    attn_edge_kernel<<<512, 256>>>(e);
    av_kernel<<<dim3(16, 8), 256>>>();
    out_kernel<<<512, 256>>>(We, Wo, bo, out);
}

// round 2
// speedup vs baseline: 1.0717x; 1.0717x over previous
#include <cuda_runtime.h>
#include <math.h>

#define L 512
#define DO 64      // D_ORIG
#define NH 8
#define DH 32
#define DE 256
#define SCALE 0.17677669529663687f  // 1/sqrt(32)

// Scratch (device globals — no allocations allowed)
__device__ float g_q[L*DE];
__device__ float g_k[L*DE];
__device__ float g_v[L*DE];
__device__ float g_p[L*512];           // [i][n*64+c]
__device__ float g_sc[(size_t)NH*L*L]; // [n][i][j] : qk base logits
__device__ float g_s[L*NH];            // softmax denominators
__device__ float g_w[L*512];           // [i][n*64+c], unnormalized edge-weight sums
__device__ float g_att[L*DE];          // unnormalized attn@v

// ---------------------------------------------------------------------------
// Kernel 1: q,k,v = x@W and p[i][n][c] = scale * sum_d We[c][n*32+d]*q[i][n*32+d]
// ---------------------------------------------------------------------------
__global__ void proj_kernel(const float* __restrict__ x, const float* __restrict__ Wq,
                            const float* __restrict__ Wk, const float* __restrict__ Wv,
                            const float* __restrict__ We) {
    int i = blockIdx.x, t = threadIdx.x;
    __shared__ float xs[DO];
    __shared__ float qs[DE];
    if (t < DO) xs[t] = x[i*DO + t];
    __syncthreads();
    float aq = 0.f, ak = 0.f, av = 0.f;
    #pragma unroll
    for (int d = 0; d < DO; d++) {
        float xv = xs[d];
        aq = fmaf(xv, Wq[d*DE + t], aq);
        ak = fmaf(xv, Wk[d*DE + t], ak);
        av = fmaf(xv, Wv[d*DE + t], av);
    }
    g_q[i*DE + t] = aq; g_k[i*DE + t] = ak; g_v[i*DE + t] = av;
    qs[t] = aq;
    __syncthreads();
    #pragma unroll
    for (int r = t; r < 512; r += 256) {
        int n = r >> 6, c = r & 63;
        float acc = 0.f;
        const float* wrow = &We[c*DE + n*DH];
        const float* qh   = &qs[n*DH];
        #pragma unroll
        for (int d = 0; d < DH; d++) acc = fmaf(wrow[d], qh[d], acc);
        g_p[i*512 + r] = acc * SCALE;
    }
}

// ---------------------------------------------------------------------------
// Kernel 2: base[n][i][j] = scale * q[i,nslice] . k[j,nslice]
// ---------------------------------------------------------------------------
__global__ void qk_kernel() {
    int n = blockIdx.z, i0 = blockIdx.y * 32, j0 = blockIdx.x * 32;
    int t = threadIdx.x;
    __shared__ float Qs[32][33], Ks[32][33];
    for (int l = t; l < 1024; l += 256) {
        int r = l >> 5, d = l & 31;
        Qs[r][d] = g_q[(i0 + r)*DE + n*DH + d];
        Ks[r][d] = g_k[(j0 + r)*DE + n*DH + d];
    }
    __syncthreads();
    int tx = t & 31, ty = t >> 5;  // ty 0..7
    float acc[4] = {0.f, 0.f, 0.f, 0.f};
    #pragma unroll
    for (int d = 0; d < 32; d++) {
        float kv = Ks[tx][d];
        #pragma unroll
        for (int m = 0; m < 4; m++) acc[m] = fmaf(Qs[ty*4 + m][d], kv, acc[m]);
    }
    #pragma unroll
    for (int m = 0; m < 4; m++)
        g_sc[((size_t)n*L + (i0 + ty*4 + m))*L + j0 + tx] = acc[m] * SCALE;
}

// ---------------------------------------------------------------------------
// Kernel 3 (hot, fully fused): per-query edge logits + online softmax +
// edge-weight accumulation + attn@v accumulation. 1 CTA per i, warp w = head w.
// e[i,:,:] streamed exactly once, register-double-buffered.
// ---------------------------------------------------------------------------
__global__ void attn_edge_kernel(const float* __restrict__ e) {
    int i = blockIdx.x, t = threadIdx.x;
    int w = t >> 5, lane = t & 31;
    __shared__ float ps[512];
    __shared__ float es[64][65];     // pad 65: conflict-free rows AND columns
    __shared__ float pes[8][64];
    ps[t]       = g_p[i*512 + t];
    ps[t + 256] = g_p[i*512 + t + 256];

    float m = -1e30f, s = 0.f, wlo = 0.f, whi = 0.f, vac = 0.f;
    const float* pn = &ps[w*64];
    const float4* esrc = (const float4*)&e[(size_t)i*L*DO];  // 16 float4 per row

    // prefetch tile 0 into registers (4 float4 per thread covers 64x64 floats)
    float4 buf[4];
    #pragma unroll
    for (int k = 0; k < 4; k++) buf[k] = esrc[t + k*256];

    for (int j0 = 0; j0 < L; j0 += 64) {
        __syncthreads();   // prev compute done (and ps ready on iter 0)
        #pragma unroll
        for (int k = 0; k < 4; k++) {
            int l = t + k*256, jj = l >> 4, c4 = (l & 15) * 4;
            es[jj][c4 + 0] = buf[k].x; es[jj][c4 + 1] = buf[k].y;
            es[jj][c4 + 2] = buf[k].z; es[jj][c4 + 3] = buf[k].w;
        }
        __syncthreads();
        if (j0 + 64 < L) {           // prefetch next tile while computing
            #pragma unroll
            for (int k = 0; k < 4; k++) buf[k] = esrc[(j0 + 64)*16 + t + k*256];
        }

        // ---- edge logits for j = j0+lane, j0+lane+32 (2 partial accums each)
        size_t base = ((size_t)w*L + i)*L + j0;
        float sc0 = g_sc[base + lane];
        float sc1 = g_sc[base + lane + 32];
        float a0 = 0.f, b0 = 0.f, a1 = 0.f, b1 = 0.f;
        #pragma unroll
        for (int c = 0; c < 64; c += 2) {
            float p0 = pn[c], p1 = pn[c + 1];
            a0 = fmaf(es[lane][c],          p0, a0);
            b0 = fmaf(es[lane][c + 1],      p1, b0);
            a1 = fmaf(es[lane + 32][c],     p0, a1);
            b1 = fmaf(es[lane + 32][c + 1], p1, b1);
        }
        sc0 += a0 + b0; sc1 += a1 + b1;

        // ---- online softmax (per-warp)
        float bm = fmaxf(sc0, sc1);
        #pragma unroll
        for (int off = 16; off; off >>= 1) bm = fmaxf(bm, __shfl_xor_sync(0xffffffffu, bm, off));
        float newm = fmaxf(m, bm);
        float alpha = __expf(m - newm);
        s *= alpha; wlo *= alpha; whi *= alpha; vac *= alpha;
        float pe0 = __expf(sc0 - newm), pe1 = __expf(sc1 - newm);
        pes[w][lane] = pe0; pes[w][lane + 32] = pe1;
        float bs = pe0 + pe1;
        #pragma unroll
        for (int off = 16; off; off >>= 1) bs += __shfl_xor_sync(0xffffffffu, bs, off);
        s += bs;
        m = newm;
        __syncwarp();

        // ---- accumulate edge-weights AND attn@v (v is L2/L1-resident)
        const float* vb = &g_v[(size_t)j0*DE + w*DH + lane];
        #pragma unroll 8
        for (int jj = 0; jj < 64; jj++) {
            float pv = pes[w][jj];
            wlo = fmaf(pv, es[jj][lane],      wlo);
            whi = fmaf(pv, es[jj][lane + 32], whi);
            vac = fmaf(pv, vb[jj*DE],         vac);
        }
    }
    g_w[i*512 + w*64 + lane]      = wlo;
    g_w[i*512 + w*64 + lane + 32] = whi;
    g_att[i*DE + w*DH + lane]     = vac;
    if (lane == 0) g_s[i*NH + w] = s;
}

// ---------------------------------------------------------------------------
// Kernel 4: att = (attv + w@We_slice)/s ; out = att@Wo + bo
// ---------------------------------------------------------------------------
__global__ void out_kernel(const float* __restrict__ We, const float* __restrict__ Wo,
                           const float* __restrict__ bo, float* __restrict__ out) {
    int i = blockIdx.x, t = threadIdx.x;
    int n = t >> 5;  // head of embedding column t
    __shared__ float att[DE];
    __shared__ float ws[512];
    ws[t] = g_w[i*512 + t];
    ws[t + 256] = g_w[i*512 + t + 256];
    __syncthreads();
    float edge = 0.f;
    const float* wn = &ws[n*64];
    #pragma unroll
    for (int c = 0; c < 64; c++) edge = fmaf(wn[c], We[c*DE + t], edge);
    float sv = g_s[i*NH + n];
    att[t] = (g_att[i*DE + t] + edge) / sv;
    __syncthreads();
    if (t < DO) {
        float o = bo[t];
        #pragma unroll 8
        for (int k = 0; k < DE; k++) o = fmaf(att[k], Wo[k*DO + t], o);
        out[i*DO + t] = o;
    }
}

// ---------------------------------------------------------------------------
extern "C" void kernel_launch(void* const* d_in, const int* in_sizes, int n_in,
                              void* d_out, int out_size) {
    const float* x  = (const float*)d_in[0];
    const float* e  = (const float*)d_in[1];
    const float* Wq = (const float*)d_in[2];
    const float* Wk = (const float*)d_in[3];
    const float* Wv = (const float*)d_in[4];
    const float* We = (const float*)d_in[5];
    const float* Wo = (const float*)d_in[6];
    const float* bo = (const float*)d_in[7];
    float* out = (float*)d_out;

    proj_kernel<<<512, 256>>>(x, Wq, Wk, Wv, We);
    qk_kernel<<<dim3(16, 16, 8), 256>>>();
    attn_edge_kernel<<<512, 256>>>(e);
    out_kernel<<<512, 256>>>(We, Wo, bo, out);
}